// round 16
// baseline (speedup 1.0000x reference)
#include <cuda_runtime.h>
#include <cstdint>

#define DIM 512
#define BATCH 32
#define M_TOTAL 131072            /* 64*64*32 */
#define MTILE 64
#define NTILES (M_TOTAL/MTILE)     /* 2048 */
#define KC 128                     /* k per chunk: 512B contiguous per U-row */
#define NCHUNK (DIM/KC)            /* 4 */
#define KSTEPS (KC/8)              /* 16 */
#define NTHREADS 128
#define A_STRIDE 132               /* words per A smem row (128+4): reads bank-free */
#define B_STRIDE 40                /* words per B smem row (R12-proven) */
#define A_CH_WORDS (MTILE*A_STRIDE)    /* 8448 */
#define B_CH_WORDS (KC*B_STRIDE)       /* 5120 */
#define SMEM_WORDS (2*(A_CH_WORDS + B_CH_WORDS))   /* 27136 words = 106 KB */

/* B operand, tf32-RNE: g_scaled[k*32+b] = rna_tf32(L[k]*style[b][k])  (k-major) */
__device__ uint32_t g_scaled[DIM * BATCH];

__global__ void prep_kernel(const float* __restrict__ style, const float* __restrict__ L) {
    int i = blockIdx.x * blockDim.x + threadIdx.x;
    if (i < DIM * BATCH) {
        int k = i >> 5, b = i & 31;
        float v = L[k] * style[b * DIM + k];
        uint32_t bits;
        asm("cvt.rna.tf32.f32 %0, %1;" : "=r"(bits) : "f"(v));
        g_scaled[i] = bits;
    }
}

__device__ __forceinline__ uint32_t smem_u32(const void* p) {
    return (uint32_t)__cvta_generic_to_shared(p);
}
__device__ __forceinline__ void cp16(uint32_t dst, const void* src) {
    asm volatile("cp.async.cg.shared.global [%0], [%1], 16;" :: "r"(dst), "l"(src));
}
/* B loads: pair adjacent 128B k-rows into one 256B L2 sector fetch */
__device__ __forceinline__ void cp16_pf(uint32_t dst, const void* src) {
    asm volatile("cp.async.cg.shared.global.L2::256B [%0], [%1], 16;" :: "r"(dst), "l"(src));
}
__device__ __forceinline__ void cp_commit() {
    asm volatile("cp.async.commit_group;" ::: "memory");
}
__device__ __forceinline__ void cp_wait1() {
    asm volatile("cp.async.wait_group 1;" ::: "memory");
}
__device__ __forceinline__ void st_cs(float* p, float v) {
    asm volatile("st.global.cs.f32 [%0], %1;" :: "l"(p), "f"(v) : "memory");
}
__device__ __forceinline__ void mma_tf32(float* d, const uint32_t* a, uint32_t b0, uint32_t b1) {
    asm volatile(
        "mma.sync.aligned.m16n8k8.row.col.f32.tf32.tf32.f32 "
        "{%0,%1,%2,%3}, {%4,%5,%6,%7}, {%8,%9}, {%0,%1,%2,%3};"
        : "+f"(d[0]), "+f"(d[1]), "+f"(d[2]), "+f"(d[3])
        : "r"(a[0]), "r"(a[1]), "r"(a[2]), "r"(a[3]), "r"(b0), "r"(b1));
}

__global__ void __launch_bounds__(NTHREADS, 2)
gemm_kernel(const float* __restrict__ U, const float* __restrict__ mu, float* __restrict__ out)
{
    extern __shared__ uint32_t smem[];          /* [A s0][A s1][B s0][B s1] */
    uint32_t* const sA0 = smem;
    uint32_t* const sB0 = smem + 2 * A_CH_WORDS;

    const int tid = threadIdx.x;
    const int wid = tid >> 5;
    const int lid = tid & 31;
    const int g   = lid >> 2;      /* groupID 0..7 */
    const int tg  = lid & 3;       /* thread-in-group 0..3 */
    const int mbase = blockIdx.x * MTILE;

    auto prefetch = [&](int c, int buf) {
        /* A: 64 rows x 512B contiguous per row (2048 16B segs, 16 iters) */
        const float* ubase = U + (size_t)mbase * DIM + c * KC;
        uint32_t adst = smem_u32(sA0 + buf * A_CH_WORDS);
        #pragma unroll
        for (int j = 0; j < 16; ++j) {
            int S = j * NTHREADS + tid;
            int row = S >> 5, seg = S & 31;
            cp16(adst + (uint32_t)(row * (A_STRIDE * 4) + seg * 16),
                 ubase + (size_t)row * DIM + seg * 4);
        }
        /* B: 128 k-rows x 128B (16KB contiguous in gmem), L2::256B pairing */
        const uint32_t* bsrc = g_scaled + c * KC * BATCH;
        uint32_t bdst = smem_u32(sB0 + buf * B_CH_WORDS);
        #pragma unroll
        for (int j = 0; j < 8; ++j) {
            int S = j * NTHREADS + tid;
            int row = S >> 3, seg = S & 7;
            cp16_pf(bdst + (uint32_t)(row * (B_STRIDE * 4) + seg * 16),
                    bsrc + (size_t)row * BATCH + seg * 4);
        }
    };

    float acc[4][4];
    #pragma unroll
    for (int nt = 0; nt < 4; ++nt)
        #pragma unroll
        for (int r = 0; r < 4; ++r) acc[nt][r] = 0.0f;

    prefetch(0, 0); cp_commit();
    prefetch(1, 1); cp_commit();

    for (int c = 0; c < NCHUNK; ++c) {
        cp_wait1();
        __syncthreads();
        const uint32_t* A = sA0 + (c & 1) * A_CH_WORDS;
        const uint32_t* B = sB0 + (c & 1) * B_CH_WORDS;

        #pragma unroll
        for (int ks = 0; ks < KSTEPS; ++ks) {
            uint32_t a[4], b[4][2];
            const int r0 = wid * 16 + g;       /* warp's m16 tile rows g, g+8 */
            /* +0x1000: RNE into tf32 (HW truncates low 13 bits) */
            a[0] = A[(r0)     * A_STRIDE + ks * 8 + tg]     + 0x1000u;
            a[1] = A[(r0 + 8) * A_STRIDE + ks * 8 + tg]     + 0x1000u;
            a[2] = A[(r0)     * A_STRIDE + ks * 8 + tg + 4] + 0x1000u;
            a[3] = A[(r0 + 8) * A_STRIDE + ks * 8 + tg + 4] + 0x1000u;
            #pragma unroll
            for (int nt = 0; nt < 4; ++nt) {
                b[nt][0] = B[(ks * 8 + tg)     * B_STRIDE + nt * 8 + g];
                b[nt][1] = B[(ks * 8 + tg + 4) * B_STRIDE + nt * 8 + g];
            }
            #pragma unroll
            for (int nt = 0; nt < 4; ++nt)
                mma_tf32(acc[nt], a, b[nt][0], b[nt][1]);
        }

        __syncthreads();
        if (c + 2 < NCHUNK) prefetch(c + 2, c & 1);
        cp_commit();   /* possibly-empty group keeps wait_group accounting simple */
    }

    /* epilogue: add mu, store out[b][m] with evict-first */
    {
        int m0 = mbase + wid * 16 + g;
        float mu0 = __ldg(&mu[m0]);
        float mu1 = __ldg(&mu[m0 + 8]);
        #pragma unroll
        for (int nt = 0; nt < 4; ++nt) {
            int b0 = nt * 8 + 2 * tg;
            st_cs(&out[(size_t)b0       * M_TOTAL + m0],     acc[nt][0] + mu0);
            st_cs(&out[(size_t)(b0 + 1) * M_TOTAL + m0],     acc[nt][1] + mu0);
            st_cs(&out[(size_t)b0       * M_TOTAL + m0 + 8], acc[nt][2] + mu1);
            st_cs(&out[(size_t)(b0 + 1) * M_TOTAL + m0 + 8], acc[nt][3] + mu1);
        }
    }
}

extern "C" void kernel_launch(void* const* d_in, const int* in_sizes, int n_in,
                              void* d_out, int out_size) {
    const float *style = nullptr, *U = nullptr, *L = nullptr, *mu = nullptr;
    for (int i = 0; i < n_in; ++i) {
        switch (in_sizes[i]) {
            case BATCH * DIM:   style = (const float*)d_in[i]; break;
            case M_TOTAL * DIM: U     = (const float*)d_in[i]; break;
            case DIM:           L     = (const float*)d_in[i]; break;
            case M_TOTAL:       mu    = (const float*)d_in[i]; break;
            default: break;
        }
    }
    float* out = (float*)d_out;

    cudaFuncSetAttribute(gemm_kernel, cudaFuncAttributeMaxDynamicSharedMemorySize,
                         SMEM_WORDS * 4);

    prep_kernel<<<(DIM * BATCH + 255) / 256, 256>>>(style, L);
    gemm_kernel<<<NTILES, NTHREADS, SMEM_WORDS * 4>>>(U, mu, out);
}